// round 16
// baseline (speedup 1.0000x reference)
#include <cuda_runtime.h>
#include <cuda_fp16.h>
#include <math.h>
#include <stdint.h>

// ---------------- problem constants ----------------
#define B_    32
#define C_    256
#define HW_   1024
#define NPOS  32768
#define NE    1024
#define EDIM  256
#define EPS_CAND 1.5e-4f
#define F16_GUARD 1e-4f
#define CAP   24

// ---------------- device scratch (no allocs allowed) ----------------
__device__ __half g_Bh[(size_t)NE * EDIM];     // 0.5 MB emb in fp16
__device__ int   g_cand[(size_t)NPOS * CAP];   // 3 MB candidate lists
__device__ int   g_ncand[NPOS];
__device__ float g_zsum[NPOS];
__device__ float g_e2[NE];
__device__ int   g_idx[NPOS];
__device__ int   g_counts[NE];
__device__ float g_loss_partial[512];

// ---------------------------------------------------------------------------
__device__ __forceinline__ uint32_t smem_u32(const void* p) {
    uint32_t a;
    asm("{ .reg .u64 t; cvta.to.shared.u64 t, %1; cvt.u32.u64 %0, t; }" : "=r"(a) : "l"(p));
    return a;
}
// order-preserving float->uint encoding for unsigned atomicMin
__device__ __forceinline__ uint32_t fenc(float f) {
    uint32_t u = __float_as_uint(f);
    return (u & 0x80000000u) ? ~u : (u | 0x80000000u);
}
__device__ __forceinline__ float fdec(uint32_t u) {
    return (u & 0x80000000u) ? __uint_as_float(u & 0x7FFFFFFFu)
                             : __uint_as_float(~u);
}
#define SMIN_INIT 0xFF7FFFFFu   // fenc(FLT_MAX): decodes to +FLT_MAX, NOT NaN

#define CP_ASYNC16(dst, src) \
    asm volatile("cp.async.ca.shared.global [%0], [%1], 16;" :: "r"(dst), "l"(src))
#define CP_COMMIT() asm volatile("cp.async.commit_group;" ::: "memory")
#define CP_WAIT0()  asm volatile("cp.async.wait_group 0;" ::: "memory")

#define LDSM_A(dst, addr) \
    asm volatile("ldmatrix.sync.aligned.m8n8.x4.shared.b16 {%0,%1,%2,%3}, [%4];" \
        : "=r"((dst)[0]), "=r"((dst)[1]), "=r"((dst)[2]), "=r"((dst)[3]) : "r"(addr))

// ---------------------------------------------------------------------------
__global__ void init_kernel() {
    int t = blockIdx.x * blockDim.x + threadIdx.x;
    if (t < NE) g_counts[t] = 0;
}

// exact ||e||^2: sequential fp32, squares rounded separately (matches ref)
__global__ void e2_kernel(const float* __restrict__ emb) {
    int row = blockIdx.x * blockDim.x + threadIdx.x;
    if (row >= NE) return;
    const float* r = emb + (size_t)row * EDIM;
    float s = 0.0f;
    for (int i = 0; i < EDIM; i++) {
        float v = r[i];
        s = __fadd_rn(s, __fmul_rn(v, v));
    }
    g_e2[row] = s;
}

// emb -> fp16 rows
__global__ void conv_e_kernel(const float* __restrict__ emb) {
    int t = blockIdx.x * 256 + threadIdx.x;
    int n = t >> 5, c0 = (t & 31) * 8;
    const float* src = emb + (size_t)n * EDIM + c0;
    __half h[8];
#pragma unroll
    for (int i = 0; i < 8; i++) h[i] = __float2half_rn(src[i]);
    *(uint4*)(&g_Bh[(size_t)n * EDIM + c0]) = *(uint4*)h;
}

// ---------------------------------------------------------------------------
// Fused: z load+transpose+fp16 convert + zsum + HMMA filter GEMM (cp.async
// B stream, fragment-double-buffered mainloop) + hybrid gating + filter.
#define A_STR 264
#define B_STR 264
#define OFF_A     0
#define OFF_B0    33792
#define OFF_B1    67584
#define OFF_STAGE 33792                        // aliases B0+B1 (66560 <= 67584)
#define OFF_E2    101376                       // float[1024] = 4096
#define OFF_CAND  105472                       // int[64*CAP]   = 6144
#define OFF_SCH   111616                       // half[64*CAP]  = 3072
#define OFF_CNT   114688                       // int[64]
#define OFF_MIN   114944                       // uint[64]
#define GEMM_SMEM 115200

extern __shared__ char gsm[];

__global__ void __launch_bounds__(256, 2)
filter_gemm_kernel(const float* __restrict__ z) {
    __half* As  = (__half*)(gsm + OFF_A);
    float* stage = (float*)(gsm + OFF_STAGE);
    float* e2s   = (float*)(gsm + OFF_E2);
    int*   sCand = (int*)(gsm + OFF_CAND);
    __half* sScH = (__half*)(gsm + OFF_SCH);
    int*   sCnt  = (int*)(gsm + OFF_CNT);
    uint32_t* sMin = (uint32_t*)(gsm + OFF_MIN);

    const int tid = threadIdx.x;
    const int lane = tid & 31, wid = tid >> 5;
    const int wm = wid >> 2, wn = wid & 3;    // 2 x 4 warp grid
    const int m0 = blockIdx.x * 64;
    const int b = m0 >> 10, hw0 = m0 & 1023;
    const int g = lane >> 2, t2 = (lane & 3) * 2;
    const unsigned full = 0xFFFFFFFFu;

    // ---- prologue: stage z tile [256 c][64 pos] (pad 65), coalesced ----
    const float* zb = z + (size_t)b * C_ * HW_ + hw0;
    for (int i = tid; i < 4096; i += 256) {
        int c = i >> 4, seg = i & 15;
        float4 v = *(const float4*)(zb + (size_t)c * HW_ + seg * 4);
        float* d = &stage[c * 65 + seg * 4];
        d[0] = v.x; d[1] = v.y; d[2] = v.z; d[3] = v.w;
    }
    for (int i = tid; i < 1024; i += 256) e2s[i] = g_e2[i];
    __syncthreads();
    // exact zsum: sequential fp32, ascending k, squares rounded separately
    if (tid < 64) {
        float s = 0.0f;
        for (int k = 0; k < EDIM; k++) {
            float v = stage[k * 65 + tid];
            s = __fadd_rn(s, __fmul_rn(v, v));
        }
        g_zsum[m0 + tid] = s;
    }
    // convert to fp16 A tile [row][k]
    for (int i = tid; i < 2048; i += 256) {
        int row = i & 63, u = i >> 6;
        __half h[8];
#pragma unroll
        for (int cc = 0; cc < 8; cc++)
            h[cc] = __float2half_rn(stage[(u * 8 + cc) * 65 + row]);
        *(uint4*)(&As[row * A_STR + u * 8]) = *(uint4*)h;
    }
    __syncthreads();                           // stage dead after this
    if (tid < 64) { sCnt[tid] = 0; sMin[tid] = SMIN_INIT; }

    const uint32_t sA = smem_u32(gsm + OFF_A);
    const uint32_t sB0 = smem_u32(gsm + OFF_B0), sB1 = smem_u32(gsm + OFF_B1);
    uint32_t aAddr[2], bOff;
#pragma unroll
    for (int i = 0; i < 2; i++)
        aAddr[i] = sA + ((wm * 32 + i * 16 + (lane & 15)) * A_STR + (lane >> 4) * 8) * 2;
    {
        int n = wn * 16 + (lane & 7) + ((lane & 16) ? 8 : 0);
        int seg = (lane & 8) ? 8 : 0;
        bOff = (n * B_STR + seg) * 2;
    }

    // this thread's 4 row-slots: slot s -> row wm*32 + (s>>1)*16 + (s&1)*8 + g
    const int rowbase = wm * 32 + g;
    int myrow[4];
#pragma unroll
    for (int s = 0; s < 4; s++) myrow[s] = rowbase + ((s >> 1) * 16) + ((s & 1) * 8);

    // per-thread cp.async slice: 8 x 16B (row = l>>5, seg = l&31)
    const int cprow = tid >> 5;
    const int cpseg = tid & 31;
#pragma unroll
    for (int q = 0; q < 8; q++) {
        int row = cprow + q * 8;
        uint32_t dst = sB0 + row * (B_STR * 2) + cpseg * 16;
        const char* src = (const char*)g_Bh + (size_t)row * 512 + cpseg * 16;
        CP_ASYNC16(dst, src);
    }
    CP_COMMIT();

    for (int nb = 0; nb < 16; nb++) {
        uint32_t bBuf = (nb & 1) ? sB1 : sB0;
        uint32_t bAddr = bBuf + bOff;
        CP_WAIT0();
        __syncthreads();                       // chunk nb visible
        if (nb + 1 < 16) {
            uint32_t nBuf = ((nb + 1) & 1) ? sB1 : sB0;
#pragma unroll
            for (int q = 0; q < 8; q++) {
                int row = cprow + q * 8;
                uint32_t dst = nBuf + row * (B_STR * 2) + cpseg * 16;
                const char* src = (const char*)g_Bh
                    + ((size_t)(nb + 1) * 64 + row) * 512 + cpseg * 16;
                CP_ASYNC16(dst, src);
            }
            CP_COMMIT();
        }

        float acc[2][2][4];
#pragma unroll
        for (int i = 0; i < 2; i++)
#pragma unroll
            for (int j = 0; j < 2; j++)
#pragma unroll
                for (int c = 0; c < 4; c++) acc[i][j][c] = 0.0f;

        // ---- fragment-double-buffered mainloop ----
        // frag buffers: [2] deep; issue ldsm for k+1 BEFORE mma for k so the
        // mma consumes fragments loaded a full iteration earlier (LDS latency
        // hidden even though every asm is volatile/in-order).
        uint32_t afr[2][2][4], bfr2[2][4];
        LDSM_A(afr[0][0], aAddr[0]);
        LDSM_A(afr[0][1], aAddr[1]);
        LDSM_A(bfr2[0],   bAddr);
#pragma unroll
        for (int kk = 0; kk < 16; kk++) {
            const int cur = kk & 1, nxt = cur ^ 1;
            if (kk + 1 < 16) {
                LDSM_A(afr[nxt][0], aAddr[0] + (kk + 1) * 32);
                LDSM_A(afr[nxt][1], aAddr[1] + (kk + 1) * 32);
                LDSM_A(bfr2[nxt],   bAddr    + (kk + 1) * 32);
            }
#pragma unroll
            for (int i = 0; i < 2; i++)
#pragma unroll
                for (int j = 0; j < 2; j++)
                    asm volatile("mma.sync.aligned.m16n8k16.row.col.f32.f16.f16.f32 "
                        "{%0,%1,%2,%3}, {%4,%5,%6,%7}, {%8,%9}, {%0,%1,%2,%3};"
                        : "+f"(acc[i][j][0]), "+f"(acc[i][j][1]),
                          "+f"(acc[i][j][2]), "+f"(acc[i][j][3])
                        : "r"(afr[cur][i][0]), "r"(afr[cur][i][1]),
                          "r"(afr[cur][i][2]), "r"(afr[cur][i][3]),
                          "r"(bfr2[cur][j * 2]), "r"(bfr2[cur][j * 2 + 1]));
        }

        // epilogue: s = e2 - 2*dot. Hybrid gating (superset-safe).
        float cm[4];
#pragma unroll
        for (int s = 0; s < 4; s++)
            cm[s] = fdec(*(volatile uint32_t*)&sMin[myrow[s]]);

#pragma unroll
        for (int i = 0; i < 2; i++)
#pragma unroll
            for (int j = 0; j < 2; j++) {
                int nl = wn * 16 + j * 8 + t2;
                int ng = nb * 64 + nl;
                float e20 = e2s[ng], e21 = e2s[ng + 1];
                float sv[4];
                sv[0] = __fadd_rn(e20, -(2.0f * acc[i][j][0]));
                sv[1] = __fadd_rn(e21, -(2.0f * acc[i][j][1]));
                sv[2] = __fadd_rn(e20, -(2.0f * acc[i][j][2]));
                sv[3] = __fadd_rn(e21, -(2.0f * acc[i][j][3]));
#pragma unroll
                for (int q = 0; q < 4; q++) {
                    int s = i * 2 + (q >> 1);
                    int col = ng + (q & 1);
                    int row = myrow[s];
                    if (nb == 0) {
                        uint32_t old = atomicMin(&sMin[row], fenc(sv[q]));
                        float c = fminf(fdec(old), sv[q]);
                        cm[s] = c;
                        if (sv[q] <= c + EPS_CAND) {
                            int p = atomicAdd(&sCnt[row], 1);
                            if (p < CAP) {
                                sCand[row * CAP + p] = col;
                                sScH[row * CAP + p] = __float2half_rn(sv[q]);
                            }
                        }
                    } else if (sv[q] <= cm[s] + EPS_CAND) {
                        if (sv[q] < cm[s]) {
                            atomicMin(&sMin[row], fenc(sv[q]));
                            cm[s] = sv[q];
                        }
                        int p = atomicAdd(&sCnt[row], 1);
                        if (p < CAP) {
                            sCand[row * CAP + p] = col;
                            sScH[row * CAP + p] = __float2half_rn(sv[q]);
                        }
                    }
                }
            }
    }
    __syncthreads();

    // final-min filter: warp w handles rows w*8..w*8+7; compact survivors.
    for (int r8 = 0; r8 < 8; r8++) {
        int row = wid * 8 + r8;
        int cnt = sCnt[row];
        if (cnt > CAP) {
            if (lane == 0) g_ncand[m0 + row] = NE;   // full-scan fallback
            continue;
        }
        float thr = fdec(sMin[row]) + EPS_CAND + F16_GUARD;
        bool keep = (lane < cnt) && (__half2float(sScH[row * CAP + lane]) <= thr);
        unsigned mask = __ballot_sync(full, keep);
        if (keep) {
            int p = __popc(mask & ((1u << lane) - 1));
            g_cand[(size_t)(m0 + row) * CAP + p] = sCand[row * CAP + lane];
        }
        if (lane == 0) g_ncand[m0 + row] = __popc(mask);
    }
}

// ---------------------------------------------------------------------------
// exact rescore of candidates; (score, index) lexicographic min ->
// bit-identical to reference argmin (first-index tie-break).
__global__ void rescore_kernel(const float* __restrict__ z,
                               const float* __restrict__ emb) {
    const int tid = threadIdx.x;
    const int wid = tid >> 5, lane = tid & 31;
    const int m = blockIdx.x * 8 + wid;
    const int b = m >> 10, hw = m & 1023;
    const unsigned full = 0xFFFFFFFFu;

    int nc = g_ncand[m];
    int bestJ;
    if (nc == 1) {
        bestJ = g_cand[(size_t)m * CAP];       // sole candidate is the argmin
    } else {
        float zsum = g_zsum[m];
        const float* zp = z + (size_t)b * C_ * HW_ + hw;
        float bestS = 0.0f; bool have = false; bestJ = -1;
        if (nc >= 2 && nc <= CAP) {
            int ci = lane < nc ? lane : nc - 1;
            int j = g_cand[(size_t)m * CAP + ci];
            const float* ep = emb + (size_t)j * EDIM;
            float acc = 0.0f;
#pragma unroll 8
            for (int k = 0; k < EDIM; k++)
                acc = __fmaf_rn(zp[(size_t)k << 10], ep[k], acc);
            float t1 = __fadd_rn(zsum, __ldg(&g_e2[j]));
            float s  = __fadd_rn(t1, -(2.0f * acc));
            for (int l = 0; l < CAP; l++) {
                float sv = __shfl_sync(full, s, l);
                int   jv = __shfl_sync(full, j, l);
                if (l < nc) {
                    if (!have || sv < bestS || (sv == bestS && jv < bestJ)) {
                        have = true; bestS = sv; bestJ = jv;
                    }
                }
            }
        } else {
            // fallback (overflow or empty): exact argmin over all 1024 codes
            for (int jb = 0; jb < 32; jb++) {
                int j = jb * 32 + lane;
                const float* ep = emb + (size_t)j * EDIM;
                float acc = 0.0f;
#pragma unroll 8
                for (int k = 0; k < EDIM; k++)
                    acc = __fmaf_rn(zp[(size_t)k << 10], ep[k], acc);
                float t1 = __fadd_rn(zsum, __ldg(&g_e2[j]));
                float s  = __fadd_rn(t1, -(2.0f * acc));
                for (int l = 0; l < 32; l++) {
                    float sv = __shfl_sync(full, s, l);
                    int   jv = __shfl_sync(full, j, l);
                    if (!have || sv < bestS || (sv == bestS && jv < bestJ)) {
                        have = true; bestS = sv; bestJ = jv;
                    }
                }
            }
        }
    }
    if (lane == 0) {
        g_idx[m] = bestJ;
        atomicAdd(&g_counts[bestJ], 1);
    }
}

// ---------------------------------------------------------------------------
// scatter z_q + loss partials; e-rows staged in smem, coalesced z/out.
__global__ void scatter_kernel(const float* __restrict__ z,
                               const float* __restrict__ emb,
                               float* __restrict__ out) {
    __shared__ float sE[64 * 257];
    __shared__ int sIdx[64];
    __shared__ float red[256];
    const int tid = threadIdx.x;
    const int pos0 = blockIdx.x * 64;
    const int b = pos0 >> 10, hw0 = pos0 & 1023;

    if (tid < 64) sIdx[tid] = g_idx[pos0 + tid];
    __syncthreads();
    for (int i = tid; i < 4096; i += 256) {
        int row = i >> 6, seg = i & 63;
        float4 v = *(const float4*)(emb + (size_t)sIdx[row] * EDIM + seg * 4);
        float* d = &sE[row * 257 + seg * 4];
        d[0] = v.x; d[1] = v.y; d[2] = v.z; d[3] = v.w;
    }
    __syncthreads();

    const int tl = tid & 63;
    const int cg = tid >> 6;
    const float* zp = z + (size_t)b * C_ * HW_ + (size_t)(cg * 64) * HW_ + hw0 + tl;
    float* op = out + (size_t)b * C_ * HW_ + (size_t)(cg * 64) * HW_ + hw0 + tl;
    const float* ep = &sE[tl * 257 + cg * 64];
    float lsum = 0.0f;
#pragma unroll 8
    for (int c = 0; c < 64; c++) {
        float zv = zp[(size_t)c * HW_];
        float e  = ep[c];
        float d  = __fadd_rn(e, -zv);
        lsum += d * d;
        op[(size_t)c * HW_] = __fadd_rn(zv, d);
    }
    red[tid] = lsum;
    __syncthreads();
    for (int o = 128; o; o >>= 1) {
        if (tid < o) red[tid] += red[tid + o];
        __syncthreads();
    }
    if (tid == 0) g_loss_partial[blockIdx.x] = red[0];
}

// ---------------------------------------------------------------------------
__global__ void final_kernel(float* __restrict__ out, int out_size) {
    __shared__ float red[256];
    int t = threadIdx.x;
    float ent = 0.0f;
    for (int k = t; k < NE; k += 256) {
        float em = (float)g_counts[k] * (1.0f / (float)NPOS);
        ent += em * logf(em + 1e-10f);
    }
    red[t] = ent;
    __syncthreads();
    for (int o = 128; o; o >>= 1) { if (t < o) red[t] += red[t + o]; __syncthreads(); }
    float perp = expf(-red[0]);
    __syncthreads();
    red[t] = g_loss_partial[t] + g_loss_partial[t + 256];
    __syncthreads();
    for (int o = 128; o; o >>= 1) { if (t < o) red[t] += red[t + o]; __syncthreads(); }
    if (t == 0) {
        float loss = 1.25f * red[0] * (1.0f / (float)((size_t)NPOS * EDIM));
        out[out_size - 2] = loss;
        out[out_size - 1] = perp;
    }
}

// ---------------------------------------------------------------------------
extern "C" void kernel_launch(void* const* d_in, const int* in_sizes, int n_in,
                              void* d_out, int out_size) {
    const float* z   = (const float*)d_in[0];
    const float* emb = (const float*)d_in[1];
    float* out = (float*)d_out;

    cudaFuncSetAttribute(filter_gemm_kernel,
                         cudaFuncAttributeMaxDynamicSharedMemorySize, GEMM_SMEM);

    init_kernel<<<4, 256>>>();
    e2_kernel<<<4, 256>>>(emb);
    conv_e_kernel<<<128, 256>>>(emb);
    filter_gemm_kernel<<<NPOS / 64, 256, GEMM_SMEM>>>(z);
    rescore_kernel<<<NPOS / 8, 256>>>(z, emb);
    scatter_kernel<<<NPOS / 64, 256>>>(z, emb, out);
    final_kernel<<<1, 256>>>(out, out_size);
}

// round 17
// speedup vs baseline: 1.1094x; 1.1094x over previous
#include <cuda_runtime.h>
#include <cuda_fp16.h>
#include <math.h>
#include <stdint.h>

// ---------------- problem constants ----------------
#define B_    32
#define C_    256
#define HW_   1024
#define NPOS  32768
#define NE    1024
#define EDIM  256
#define EPS_CAND 1.5e-4f
#define F16_GUARD 1e-4f
#define CAP   24

// ---------------- device scratch (no allocs allowed) ----------------
// g_Bh layout: code n, 16B-seg s stored at byte n*512 + ((s ^ (n&7))*16)
// (gmem pre-swizzle so cp.async.bulk lands bank-conflict-free for ldsm)
__device__ __align__(128) __half g_Bh[(size_t)NE * EDIM];
__device__ int   g_cand[(size_t)NPOS * CAP];
__device__ int   g_ncand[NPOS];
__device__ float g_zsum[NPOS];
__device__ float g_e2[NE];
__device__ int   g_idx[NPOS];
__device__ int   g_counts[NE];
__device__ float g_loss_partial[512];

// ---------------------------------------------------------------------------
__device__ __forceinline__ uint32_t smem_u32(const void* p) {
    uint32_t a;
    asm("{ .reg .u64 t; cvta.to.shared.u64 t, %1; cvt.u32.u64 %0, t; }" : "=r"(a) : "l"(p));
    return a;
}
__device__ __forceinline__ uint32_t fenc(float f) {
    uint32_t u = __float_as_uint(f);
    return (u & 0x80000000u) ? ~u : (u | 0x80000000u);
}
__device__ __forceinline__ float fdec(uint32_t u) {
    return (u & 0x80000000u) ? __uint_as_float(u & 0x7FFFFFFFu)
                             : __uint_as_float(~u);
}
#define SMIN_INIT 0xFF7FFFFFu   // fenc(FLT_MAX)

#define MBAR_INIT(mbar, cnt) \
    asm volatile("mbarrier.init.shared.b64 [%0], %1;" :: "r"(mbar), "r"(cnt) : "memory")
#define MBAR_EXPECT_TX(mbar, bytes) \
    asm volatile("mbarrier.arrive.expect_tx.shared.b64 _, [%0], %1;" \
                 :: "r"(mbar), "r"(bytes) : "memory")
#define MBAR_WAIT(mbar, parity) do { \
    uint32_t _m = (mbar); uint32_t _p = (parity); uint32_t _done; \
    asm volatile("{\n\t.reg .pred p;\n\t" \
        "mbarrier.try_wait.parity.acquire.cta.shared::cta.b64 p, [%1], %2;\n\t" \
        "selp.b32 %0, 1, 0, p;\n\t}" : "=r"(_done) : "r"(_m), "r"(_p) : "memory"); \
    if (!_done) { \
        asm volatile("{\n\t.reg .pred P1;\n\tWL_%=: \n\t" \
            "mbarrier.try_wait.parity.acquire.cta.shared::cta.b64 P1, [%0], %1, 0x989680;\n\t" \
            "@P1 bra.uni WD_%=;\n\tbra.uni WL_%=;\n\tWD_%=: \n\t}" \
            :: "r"(_m), "r"(_p) : "memory"); \
    } } while (0)
#define BULK_CP(dst, src, bytes, mbar) \
    asm volatile("cp.async.bulk.shared::cluster.global.mbarrier::complete_tx::bytes " \
                 "[%0], [%1], %2, [%3];" \
                 :: "r"(dst), "l"(src), "r"(bytes), "r"(mbar) : "memory")

#define LDSM_X4(dst, addr) \
    asm volatile("ldmatrix.sync.aligned.m8n8.x4.shared.b16 {%0,%1,%2,%3}, [%4];" \
        : "=r"((dst)[0]), "=r"((dst)[1]), "=r"((dst)[2]), "=r"((dst)[3]) : "r"(addr))

// ---------------------------------------------------------------------------
__global__ void init_kernel() {
    int t = blockIdx.x * blockDim.x + threadIdx.x;
    if (t < NE) g_counts[t] = 0;
}

// exact ||e||^2: sequential fp32, squares rounded separately (matches ref)
__global__ void e2_kernel(const float* __restrict__ emb) {
    int row = blockIdx.x * blockDim.x + threadIdx.x;
    if (row >= NE) return;
    const float* r = emb + (size_t)row * EDIM;
    float s = 0.0f;
    for (int i = 0; i < EDIM; i++) {
        float v = r[i];
        s = __fadd_rn(s, __fmul_rn(v, v));
    }
    g_e2[row] = s;
}

// emb -> fp16 rows, gmem-swizzled: seg s of code n stored at seg (s ^ (n&7))
__global__ void conv_e_kernel(const float* __restrict__ emb) {
    int t = blockIdx.x * 256 + threadIdx.x;
    int n = t >> 5, s = t & 31;
    const float* src = emb + (size_t)n * EDIM + s * 8;
    __half h[8];
#pragma unroll
    for (int i = 0; i < 8; i++) h[i] = __float2half_rn(src[i]);
    int sw = s ^ (n & 7);
    *(uint4*)(&g_Bh[(size_t)n * EDIM + sw * 8]) = *(uint4*)h;
}

// ---------------------------------------------------------------------------
// Fused: z transpose/convert + zsum + HMMA filter GEMM with cp.async.bulk
// B streaming (double-buffered, mbarrier) + hybrid gating + final filter.
#define A_STR 264
#define OFF_A     0                            // 64*264*2 = 33792
#define OFF_B0    33792                        // 64*512   = 32768
#define OFF_B1    66560                        // 32768 -> ends 99328
#define OFF_STAGE 33792                        // stage 66560 B aliases B0+B1(+1KB)
#define OFF_E2    100352                       // float[1024] -> 104448
#define OFF_CAND  104448                       // int[64*CAP] -> 110592
#define OFF_SCH   110592                       // half[64*CAP] -> 113664
#define OFF_CNT   113664                       // -> 113920
#define OFF_MIN   113920                       // -> 114176
#define OFF_MBAR  114176                       // 2 x u64 -> 114192
#define GEMM_SMEM 114432

extern __shared__ char gsm[];

__global__ void __launch_bounds__(256, 2)
filter_gemm_kernel(const float* __restrict__ z) {
    __half* As  = (__half*)(gsm + OFF_A);
    float* stage = (float*)(gsm + OFF_STAGE);
    float* e2s   = (float*)(gsm + OFF_E2);
    int*   sCand = (int*)(gsm + OFF_CAND);
    __half* sScH = (__half*)(gsm + OFF_SCH);
    int*   sCnt  = (int*)(gsm + OFF_CNT);
    uint32_t* sMin = (uint32_t*)(gsm + OFF_MIN);

    const int tid = threadIdx.x;
    const int lane = tid & 31, wid = tid >> 5;
    const int wm = wid >> 2, wn = wid & 3;    // 2 x 4 warp grid
    const int m0 = blockIdx.x * 64;
    const int b = m0 >> 10, hw0 = m0 & 1023;
    const int g = lane >> 2, t2 = (lane & 3) * 2;
    const unsigned full = 0xFFFFFFFFu;
    const uint32_t mb0 = smem_u32(gsm + OFF_MBAR), mb1 = mb0 + 8;

    if (tid == 0) { MBAR_INIT(mb0, 1); MBAR_INIT(mb1, 1); }

    // ---- prologue: stage z tile [256 c][64 pos] (pad 65), coalesced ----
    const float* zb = z + (size_t)b * C_ * HW_ + hw0;
    for (int i = tid; i < 4096; i += 256) {
        int c = i >> 4, seg = i & 15;
        float4 v = *(const float4*)(zb + (size_t)c * HW_ + seg * 4);
        float* d = &stage[c * 65 + seg * 4];
        d[0] = v.x; d[1] = v.y; d[2] = v.z; d[3] = v.w;
    }
    for (int i = tid; i < 1024; i += 256) e2s[i] = g_e2[i];
    __syncthreads();
    // exact zsum: sequential fp32, ascending k, squares rounded separately
    if (tid < 64) {
        float s = 0.0f;
        for (int k = 0; k < EDIM; k++) {
            float v = stage[k * 65 + tid];
            s = __fadd_rn(s, __fmul_rn(v, v));
        }
        g_zsum[m0 + tid] = s;
    }
    // convert to fp16 A tile [row][k]
    for (int i = tid; i < 2048; i += 256) {
        int row = i & 63, u = i >> 6;
        __half h[8];
#pragma unroll
        for (int cc = 0; cc < 8; cc++)
            h[cc] = __float2half_rn(stage[(u * 8 + cc) * 65 + row]);
        *(uint4*)(&As[row * A_STR + u * 8]) = *(uint4*)h;
    }
    __syncthreads();                           // stage dead; mbars visible
    if (tid < 64) { sCnt[tid] = 0; sMin[tid] = SMIN_INIT; }

    const uint32_t sA = smem_u32(gsm + OFF_A);
    const uint32_t sB0 = smem_u32(gsm + OFF_B0), sB1 = smem_u32(gsm + OFF_B1);
    uint32_t aAddr[2];
#pragma unroll
    for (int i = 0; i < 2; i++)
        aAddr[i] = sA + ((wm * 32 + i * 16 + (lane & 15)) * A_STR + (lane >> 4) * 8) * 2;
    // B fragment lane geometry: n (code within chunk), khalf, swizzle key
    const int nB    = wn * 16 + (lane & 7) + ((lane & 16) ? 8 : 0);
    const int khalf = (lane & 8) ? 1 : 0;
    const int nx7   = nB & 7;
    const uint32_t bRow = (uint32_t)nB * 512;

    const int rowbase = wm * 32 + g;
    int myrow[4];
#pragma unroll
    for (int s = 0; s < 4; s++) myrow[s] = rowbase + ((s >> 1) * 16) + ((s & 1) * 8);

    // issue chunk 0 bulk copy
    if (tid == 0) {
        MBAR_EXPECT_TX(mb0, 32768u);
        BULK_CP(sB0, (const char*)g_Bh, 32768u, mb0);
    }

    int ph0 = 0, ph1 = 0;
    for (int nb = 0; nb < 16; nb++) {
        uint32_t mcur = (nb & 1) ? mb1 : mb0;
        uint32_t bBuf = (nb & 1) ? sB1 : sB0;
        if (nb & 1) { MBAR_WAIT(mcur, ph1); ph1 ^= 1; }
        else        { MBAR_WAIT(mcur, ph0); ph0 ^= 1; }
        __syncthreads();                       // all warps done with other buf
        if (nb + 1 < 16 && tid == 0) {
            uint32_t mnxt = ((nb + 1) & 1) ? mb1 : mb0;
            uint32_t nBuf = ((nb + 1) & 1) ? sB1 : sB0;
            MBAR_EXPECT_TX(mnxt, 32768u);
            BULK_CP(nBuf, (const char*)g_Bh + (size_t)(nb + 1) * 32768, 32768u, mnxt);
        }

        float acc[2][2][4];
#pragma unroll
        for (int i = 0; i < 2; i++)
#pragma unroll
            for (int j = 0; j < 2; j++)
#pragma unroll
                for (int c = 0; c < 4; c++) acc[i][j][c] = 0.0f;

        const uint32_t bBase = bBuf + bRow;
#pragma unroll 4
        for (int kk = 0; kk < 16; kk++) {
            uint32_t a[2][4], bfr[4];
#pragma unroll
            for (int i = 0; i < 2; i++)
                LDSM_X4(a[i], aAddr[i] + kk * 32);
            // swizzled B address: seg = (2kk + khalf) ^ (n & 7)
            LDSM_X4(bfr, bBase + ((uint32_t)((kk * 2 + khalf) ^ nx7) << 4));
#pragma unroll
            for (int i = 0; i < 2; i++)
#pragma unroll
                for (int j = 0; j < 2; j++)
                    asm volatile("mma.sync.aligned.m16n8k16.row.col.f32.f16.f16.f32 "
                        "{%0,%1,%2,%3}, {%4,%5,%6,%7}, {%8,%9}, {%0,%1,%2,%3};"
                        : "+f"(acc[i][j][0]), "+f"(acc[i][j][1]),
                          "+f"(acc[i][j][2]), "+f"(acc[i][j][3])
                        : "r"(a[i][0]), "r"(a[i][1]), "r"(a[i][2]), "r"(a[i][3]),
                          "r"(bfr[j * 2]), "r"(bfr[j * 2 + 1]));
        }

        // epilogue: s = e2 - 2*dot. Hybrid gating (superset-safe).
        float cm[4];
#pragma unroll
        for (int s = 0; s < 4; s++)
            cm[s] = fdec(*(volatile uint32_t*)&sMin[myrow[s]]);

#pragma unroll
        for (int i = 0; i < 2; i++)
#pragma unroll
            for (int j = 0; j < 2; j++) {
                int nl = wn * 16 + j * 8 + t2;
                int ng = nb * 64 + nl;
                float e20 = e2s[ng], e21 = e2s[ng + 1];
                float sv[4];
                sv[0] = __fadd_rn(e20, -(2.0f * acc[i][j][0]));
                sv[1] = __fadd_rn(e21, -(2.0f * acc[i][j][1]));
                sv[2] = __fadd_rn(e20, -(2.0f * acc[i][j][2]));
                sv[3] = __fadd_rn(e21, -(2.0f * acc[i][j][3]));
#pragma unroll
                for (int q = 0; q < 4; q++) {
                    int s = i * 2 + (q >> 1);
                    int col = ng + (q & 1);
                    int row = myrow[s];
                    if (nb == 0) {
                        uint32_t old = atomicMin(&sMin[row], fenc(sv[q]));
                        float c = fminf(fdec(old), sv[q]);
                        cm[s] = c;
                        if (sv[q] <= c + EPS_CAND) {
                            int p = atomicAdd(&sCnt[row], 1);
                            if (p < CAP) {
                                sCand[row * CAP + p] = col;
                                sScH[row * CAP + p] = __float2half_rn(sv[q]);
                            }
                        }
                    } else if (sv[q] <= cm[s] + EPS_CAND) {
                        if (sv[q] < cm[s]) {
                            atomicMin(&sMin[row], fenc(sv[q]));
                            cm[s] = sv[q];
                        }
                        int p = atomicAdd(&sCnt[row], 1);
                        if (p < CAP) {
                            sCand[row * CAP + p] = col;
                            sScH[row * CAP + p] = __float2half_rn(sv[q]);
                        }
                    }
                }
            }
    }
    __syncthreads();

    // final-min filter: warp w handles rows w*8..w*8+7; compact survivors.
    for (int r8 = 0; r8 < 8; r8++) {
        int row = wid * 8 + r8;
        int cnt = sCnt[row];
        if (cnt > CAP) {
            if (lane == 0) g_ncand[m0 + row] = NE;   // full-scan fallback
            continue;
        }
        float thr = fdec(sMin[row]) + EPS_CAND + F16_GUARD;
        bool keep = (lane < cnt) && (__half2float(sScH[row * CAP + lane]) <= thr);
        unsigned mask = __ballot_sync(full, keep);
        if (keep) {
            int p = __popc(mask & ((1u << lane) - 1));
            g_cand[(size_t)(m0 + row) * CAP + p] = sCand[row * CAP + lane];
        }
        if (lane == 0) g_ncand[m0 + row] = __popc(mask);
    }
}

// ---------------------------------------------------------------------------
// exact rescore of candidates; (score, index) lexicographic min ->
// bit-identical to reference argmin (first-index tie-break).
__global__ void rescore_kernel(const float* __restrict__ z,
                               const float* __restrict__ emb) {
    const int tid = threadIdx.x;
    const int wid = tid >> 5, lane = tid & 31;
    const int m = blockIdx.x * 8 + wid;
    const int b = m >> 10, hw = m & 1023;
    const unsigned full = 0xFFFFFFFFu;

    int nc = g_ncand[m];
    int bestJ;
    if (nc == 1) {
        bestJ = g_cand[(size_t)m * CAP];
    } else {
        float zsum = g_zsum[m];
        const float* zp = z + (size_t)b * C_ * HW_ + hw;
        float bestS = 0.0f; bool have = false; bestJ = -1;
        if (nc >= 2 && nc <= CAP) {
            int ci = lane < nc ? lane : nc - 1;
            int j = g_cand[(size_t)m * CAP + ci];
            const float* ep = emb + (size_t)j * EDIM;
            float acc = 0.0f;
#pragma unroll 8
            for (int k = 0; k < EDIM; k++)
                acc = __fmaf_rn(zp[(size_t)k << 10], ep[k], acc);
            float t1 = __fadd_rn(zsum, __ldg(&g_e2[j]));
            float s  = __fadd_rn(t1, -(2.0f * acc));
            for (int l = 0; l < CAP; l++) {
                float sv = __shfl_sync(full, s, l);
                int   jv = __shfl_sync(full, j, l);
                if (l < nc) {
                    if (!have || sv < bestS || (sv == bestS && jv < bestJ)) {
                        have = true; bestS = sv; bestJ = jv;
                    }
                }
            }
        } else {
            for (int jb = 0; jb < 32; jb++) {
                int j = jb * 32 + lane;
                const float* ep = emb + (size_t)j * EDIM;
                float acc = 0.0f;
#pragma unroll 8
                for (int k = 0; k < EDIM; k++)
                    acc = __fmaf_rn(zp[(size_t)k << 10], ep[k], acc);
                float t1 = __fadd_rn(zsum, __ldg(&g_e2[j]));
                float s  = __fadd_rn(t1, -(2.0f * acc));
                for (int l = 0; l < 32; l++) {
                    float sv = __shfl_sync(full, s, l);
                    int   jv = __shfl_sync(full, j, l);
                    if (!have || sv < bestS || (sv == bestS && jv < bestJ)) {
                        have = true; bestS = sv; bestJ = jv;
                    }
                }
            }
        }
    }
    if (lane == 0) {
        g_idx[m] = bestJ;
        atomicAdd(&g_counts[bestJ], 1);
    }
}

// ---------------------------------------------------------------------------
// scatter z_q + loss partials; e-rows staged in smem, coalesced z/out.
__global__ void scatter_kernel(const float* __restrict__ z,
                               const float* __restrict__ emb,
                               float* __restrict__ out) {
    __shared__ float sE[64 * 257];
    __shared__ int sIdx[64];
    __shared__ float red[256];
    const int tid = threadIdx.x;
    const int pos0 = blockIdx.x * 64;
    const int b = pos0 >> 10, hw0 = pos0 & 1023;

    if (tid < 64) sIdx[tid] = g_idx[pos0 + tid];
    __syncthreads();
    for (int i = tid; i < 4096; i += 256) {
        int row = i >> 6, seg = i & 63;
        float4 v = *(const float4*)(emb + (size_t)sIdx[row] * EDIM + seg * 4);
        float* d = &sE[row * 257 + seg * 4];
        d[0] = v.x; d[1] = v.y; d[2] = v.z; d[3] = v.w;
    }
    __syncthreads();

    const int tl = tid & 63;
    const int cg = tid >> 6;
    const float* zp = z + (size_t)b * C_ * HW_ + (size_t)(cg * 64) * HW_ + hw0 + tl;
    float* op = out + (size_t)b * C_ * HW_ + (size_t)(cg * 64) * HW_ + hw0 + tl;
    const float* ep = &sE[tl * 257 + cg * 64];
    float lsum = 0.0f;
#pragma unroll 8
    for (int c = 0; c < 64; c++) {
        float zv = zp[(size_t)c * HW_];
        float e  = ep[c];
        float d  = __fadd_rn(e, -zv);
        lsum += d * d;
        op[(size_t)c * HW_] = __fadd_rn(zv, d);
    }
    red[tid] = lsum;
    __syncthreads();
    for (int o = 128; o; o >>= 1) {
        if (tid < o) red[tid] += red[tid + o];
        __syncthreads();
    }
    if (tid == 0) g_loss_partial[blockIdx.x] = red[0];
}

// ---------------------------------------------------------------------------
__global__ void final_kernel(float* __restrict__ out, int out_size) {
    __shared__ float red[256];
    int t = threadIdx.x;
    float ent = 0.0f;
    for (int k = t; k < NE; k += 256) {
        float em = (float)g_counts[k] * (1.0f / (float)NPOS);
        ent += em * logf(em + 1e-10f);
    }
    red[t] = ent;
    __syncthreads();
    for (int o = 128; o; o >>= 1) { if (t < o) red[t] += red[t + o]; __syncthreads(); }
    float perp = expf(-red[0]);
    __syncthreads();
    red[t] = g_loss_partial[t] + g_loss_partial[t + 256];
    __syncthreads();
    for (int o = 128; o; o >>= 1) { if (t < o) red[t] += red[t + o]; __syncthreads(); }
    if (t == 0) {
        float loss = 1.25f * red[0] * (1.0f / (float)((size_t)NPOS * EDIM));
        out[out_size - 2] = loss;
        out[out_size - 1] = perp;
    }
}

// ---------------------------------------------------------------------------
extern "C" void kernel_launch(void* const* d_in, const int* in_sizes, int n_in,
                              void* d_out, int out_size) {
    const float* z   = (const float*)d_in[0];
    const float* emb = (const float*)d_in[1];
    float* out = (float*)d_out;

    cudaFuncSetAttribute(filter_gemm_kernel,
                         cudaFuncAttributeMaxDynamicSharedMemorySize, GEMM_SMEM);

    init_kernel<<<4, 256>>>();
    e2_kernel<<<4, 256>>>(emb);
    conv_e_kernel<<<128, 256>>>(emb);
    filter_gemm_kernel<<<NPOS / 64, 256, GEMM_SMEM>>>(z);
    rescore_kernel<<<NPOS / 8, 256>>>(z, emb);
    scatter_kernel<<<NPOS / 64, 256>>>(z, emb, out);
    final_kernel<<<1, 256>>>(out, out_size);
}